// round 4
// baseline (speedup 1.0000x reference)
#include <cuda_runtime.h>
#include <cuda_bf16.h>

// Problem constants
static constexpr int kS   = 256;
static constexpr int kB   = 16;
static constexpr int kV   = 32000;
static constexpr int kEMB = 32;
static constexpr int kHID = 16;
static constexpr int kG   = 4 * kHID;      // 64 gates
static constexpr int kRows = kS * kB;      // 4096
static constexpr int kRT  = 16;            // rows per logits block
static constexpr int kTile = 512;          // W_out columns staged per iter
static constexpr int kThr  = 256;          // logits threads (2 cols each)
static constexpr int kPad  = 33;           // smem row pad (conflict-free)

static constexpr int kSmemFloats = kTile * kPad;               // 16896
static constexpr int kSmemBytes  = kSmemFloats * 4             // w_smT
                                 + kRT * 32 * 8                // cpk
                                 + kRT * 4 * 2 + 64;           // s_sh, lz

// Scratch (static __device__ — no allocations allowed)
__device__ float g_gx[kS * kB * kG];
__device__ float g_concat[kS * kB * 2 * kHID];
__device__ float g_lz[kRows];              // per-row log(sum(exp(logit)))

__device__ __forceinline__ float sigf(float x) {
    return 1.0f / (1.0f + __expf(-x));
}
__device__ __forceinline__ float tanhfast(float x) {
    return 2.0f / (1.0f + __expf(-2.0f * x)) - 1.0f;
}

__device__ __forceinline__ unsigned long long pk2(float lo, float hi) {
    unsigned long long r;
    asm("mov.b64 %0, {%1, %2};" : "=l"(r) : "f"(lo), "f"(hi));
    return r;
}
__device__ __forceinline__ float lo32(unsigned long long v) {
    return __uint_as_float((unsigned)v);
}
__device__ __forceinline__ float hi32(unsigned long long v) {
    return __uint_as_float((unsigned)(v >> 32));
}
#define FMA2(acc, a, b) \
    asm("fma.rn.f32x2 %0, %1, %2, %3;" : "=l"(acc) : "l"(a), "l"(b), "l"(acc))

// ---------------------------------------------------------------------------
// Kernel 0: Gx = x@W_ih.T + b_ih + b_hh (shared by both directions)
// ---------------------------------------------------------------------------
__global__ void gx_kernel(const int* __restrict__ tokens,
                          const float* __restrict__ emb,
                          const float* __restrict__ W_ih,
                          const float* __restrict__ b_ih,
                          const float* __restrict__ b_hh) {
    __shared__ float ws[kG * 33];
    __shared__ float xs[4][32];
    __shared__ float bb[kG];

    int tid = threadIdx.x;
    for (int i = tid; i < kG * kEMB; i += 256)
        ws[(i >> 5) * 33 + (i & 31)] = W_ih[i];
    if (tid < kG) bb[tid] = b_ih[tid] + b_hh[tid];

    int sb0 = blockIdx.x * 4;
    if (tid < 128) {
        int g = tid >> 5, k = tid & 31;
        xs[g][k] = emb[(size_t)tokens[sb0 + g] * kEMB + k];
    }
    __syncthreads();

    int g = tid >> 6;
    int j = tid & (kG - 1);
    const float* wr = ws + j * 33;
    float a0 = bb[j], a1 = 0.f, a2 = 0.f, a3 = 0.f;
#pragma unroll
    for (int k = 0; k < kEMB; k += 4) {
        a0 += xs[g][k + 0] * wr[k + 0];
        a1 += xs[g][k + 1] * wr[k + 1];
        a2 += xs[g][k + 2] * wr[k + 2];
        a3 += xs[g][k + 3] * wr[k + 3];
    }
    g_gx[(sb0 + g) * kG + j] = (a0 + a1) + (a2 + a3);
}

// ---------------------------------------------------------------------------
// Kernel 1: LSTM recurrence. 32 blocks = (2 dirs) x (16 batch lanes).
// ---------------------------------------------------------------------------
__global__ void lstm_kernel(const float* __restrict__ W_hh,
                            const float* __restrict__ init_h,
                            const float* __restrict__ init_c) {
    int dir = blockIdx.x >> 4;
    int b   = blockIdx.x & 15;
    int j   = threadIdx.x;

    __shared__ float h_sh[kHID];
    __shared__ float gact[kG];

    float w[kHID];
#pragma unroll
    for (int k = 0; k < kHID; ++k) w[k] = W_hh[j * kHID + k];

    float c_reg = 0.f, h_reg = 0.f;
    if (j < kHID) {
        h_reg = init_h[j];
        c_reg = init_c[j];
        h_sh[j] = h_reg;
    }
    __syncthreads();

    int p  = dir ? (kS - 1) : 0;
    int dp = dir ? -1 : 1;
    float gx_next = g_gx[(p * kB + b) * kG + j];

    for (int step = 0; step < kS; ++step, p += dp) {
        float gxv = gx_next;
        if (step < kS - 1) gx_next = g_gx[((p + dp) * kB + b) * kG + j];

        if (j < kHID)
            g_concat[(p * kB + b) * (2 * kHID) + dir * kHID + j] = h_reg;

        float a0 = 0.f, a1 = 0.f, a2 = 0.f, a3 = 0.f;
#pragma unroll
        for (int k = 0; k < kHID; k += 4) {
            a0 += w[k + 0] * h_sh[k + 0];
            a1 += w[k + 1] * h_sh[k + 1];
            a2 += w[k + 2] * h_sh[k + 2];
            a3 += w[k + 3] * h_sh[k + 3];
        }
        float pre = gxv + ((a0 + a1) + (a2 + a3));
        gact[j] = (j >= 32 && j < 48) ? tanhfast(pre) : sigf(pre);
        __syncthreads();

        if (j < kHID) {
            float ig = gact[j];
            float fg = gact[kHID + j];
            float gg = gact[2 * kHID + j];
            float og = gact[3 * kHID + j];
            c_reg = fg * c_reg + ig * gg;
            h_reg = og * tanhfast(c_reg);
            h_sh[j] = h_reg;
        }
        __syncthreads();
    }
}

// ---------------------------------------------------------------------------
// Kernel 2: two-pass logits.
//   Pass 1 (WRITE=false): GEMM, accumulate per-row sum(exp), emit g_lz.
//                         No stores, no store addressing -> low reg pressure.
//   Pass 2 (WRITE=true):  GEMM with acc init = bias - lz  -> final log-prob
//                         written once. No expf, no s[] -> low reg pressure.
// Both: 256 threads, 2 cols/thread, weights in 32 packed u64 regs,
// 16 rows/block, concat broadcast from smem as ulonglong2.
// ---------------------------------------------------------------------------
template <bool WRITE>
__global__ void __launch_bounds__(kThr, 2)
logits_pass(const float* __restrict__ W_out,
            const float* __restrict__ b_out,
            float* __restrict__ out) {
    extern __shared__ float sm[];
    float* w_smT = sm;                                            // [512][33]
    unsigned long long* cpk =
        reinterpret_cast<unsigned long long*>(sm + kSmemFloats);  // [16][32]
    float* s_sh = reinterpret_cast<float*>(cpk + kRT * 32);
    float* lz   = s_sh + kRT;

    int row0 = blockIdx.x * kRT;
    int tid  = threadIdx.x;
    int c0   = tid * 2;

    if (tid < kRT) {
        s_sh[tid] = 0.f;
        lz[tid]   = WRITE ? g_lz[row0 + tid] : 0.f;
    }
    for (int i = tid; i < kRT * 32; i += kThr) {
        float v = g_concat[row0 * 32 + i];
        cpk[i] = pk2(v, v);
    }

    float s[kRT];
    if (!WRITE) {
#pragma unroll
        for (int r = 0; r < kRT; ++r) s[r] = 0.f;
    }

    for (int it = 0; it < 63; ++it) {
        int col0  = it * kTile;
        int ncols = min(kTile, kV - col0);

        __syncthreads();  // prev-iter readers done (also covers cpk/lz init)
        const float4* g4 = reinterpret_cast<const float4*>(
            W_out + (size_t)col0 * 32);
        int n4 = ncols * 8;
        for (int i = tid; i < n4; i += kThr) {
            float4 f = g4[i];
            float* p = w_smT + (i >> 3) * kPad + (i & 7) * 4;
            p[0] = f.x; p[1] = f.y; p[2] = f.z; p[3] = f.w;
        }
        __syncthreads();

        if (c0 < ncols) {
            unsigned long long w[32];
            const float* pa = w_smT + c0 * kPad;
            const float* pb = pa + kPad;
#pragma unroll
            for (int k = 0; k < 32; ++k) w[k] = pk2(pa[k], pb[k]);
            float2 bo = *reinterpret_cast<const float2*>(b_out + col0 + c0);

#pragma unroll
            for (int r = 0; r < kRT; r += 2) {
                unsigned long long a0, a1;
                if (WRITE) {
                    float z0 = lz[r], z1 = lz[r + 1];
                    a0 = pk2(bo.x - z0, bo.y - z0);
                    a1 = pk2(bo.x - z1, bo.y - z1);
                } else {
                    a0 = pk2(bo.x, bo.y);
                    a1 = a0;
                }
                const ulonglong2* cb0 =
                    reinterpret_cast<const ulonglong2*>(cpk + r * 32);
                const ulonglong2* cb1 =
                    reinterpret_cast<const ulonglong2*>(cpk + (r + 1) * 32);
#pragma unroll
                for (int q = 0; q < 16; ++q) {
                    ulonglong2 x0 = cb0[q];
                    ulonglong2 x1 = cb1[q];
                    FMA2(a0, w[2 * q + 0], x0.x);
                    FMA2(a1, w[2 * q + 0], x1.x);
                    FMA2(a0, w[2 * q + 1], x0.y);
                    FMA2(a1, w[2 * q + 1], x1.y);
                }
                if (WRITE) {
                    *reinterpret_cast<float2*>(
                        out + (size_t)(row0 + r) * kV + col0 + c0) =
                        make_float2(lo32(a0), hi32(a0));
                    *reinterpret_cast<float2*>(
                        out + (size_t)(row0 + r + 1) * kV + col0 + c0) =
                        make_float2(lo32(a1), hi32(a1));
                } else {
                    s[r]     += __expf(lo32(a0)) + __expf(hi32(a0));
                    s[r + 1] += __expf(lo32(a1)) + __expf(hi32(a1));
                }
            }
        }
    }

    if (!WRITE) {
        // reduce per-row sums; |logit| bounded -> raw expf sum is fp32-safe
#pragma unroll
        for (int r = 0; r < kRT; ++r) {
            float v = s[r];
#pragma unroll
            for (int off = 16; off; off >>= 1)
                v += __shfl_xor_sync(0xffffffffu, v, off);
            if ((tid & 31) == 0) atomicAdd(&s_sh[r], v);
        }
        __syncthreads();
        if (tid < kRT) g_lz[row0 + tid] = __logf(s_sh[tid]);
    }
}

// ---------------------------------------------------------------------------
extern "C" void kernel_launch(void* const* d_in, const int* in_sizes, int n_in,
                              void* d_out, int out_size) {
    const int*   tokens = (const int*)d_in[0];
    const float* emb    = (const float*)d_in[1];
    const float* W_ih   = (const float*)d_in[2];
    const float* W_hh   = (const float*)d_in[3];
    const float* b_ih   = (const float*)d_in[4];
    const float* b_hh   = (const float*)d_in[5];
    const float* W_out  = (const float*)d_in[6];
    const float* b_out  = (const float*)d_in[7];
    const float* init_h = (const float*)d_in[8];
    const float* init_c = (const float*)d_in[9];
    float* out = (float*)d_out;

    static bool attr_set = false;
    if (!attr_set) {
        cudaFuncSetAttribute(logits_pass<false>,
                             cudaFuncAttributeMaxDynamicSharedMemorySize,
                             kSmemBytes);
        cudaFuncSetAttribute(logits_pass<true>,
                             cudaFuncAttributeMaxDynamicSharedMemorySize,
                             kSmemBytes);
        attr_set = true;
    }

    gx_kernel<<<(kS * kB) / 4, 256>>>(tokens, emb, W_ih, b_ih, b_hh);
    lstm_kernel<<<32, 64>>>(W_hh, init_h, init_c);
    logits_pass<false><<<kRows / kRT, kThr, kSmemBytes>>>(W_out, b_out, out);
    logits_pass<true><<<kRows / kRT, kThr, kSmemBytes>>>(W_out, b_out, out);
}

// round 5
// speedup vs baseline: 2.5510x; 2.5510x over previous
#include <cuda_runtime.h>
#include <cuda_bf16.h>
#include <cstdint>

// Problem constants
static constexpr int kS    = 256;
static constexpr int kB    = 16;
static constexpr int kV    = 32000;
static constexpr int kEMB  = 32;
static constexpr int kHID  = 16;
static constexpr int kG    = 4 * kHID;     // 64 gates
static constexpr int kRows = kS * kB;      // 4096
static constexpr int kMT   = 128;          // rows per CTA (m tile)
static constexpr int kNT   = 128;          // cols per CTA (n tile)
static constexpr int kNTiles = kV / kNT;   // 250
static constexpr int kMTiles = kRows / kMT; // 32
static constexpr int kAPad = 36;           // padded k-stride (bank-perfect frags)

// Scratch (static __device__ — no allocations allowed)
__device__ float g_gx[kS * kB * kG];
__device__ float g_concat[kRows * 2 * kHID];          // A matrix [4096][32]
__device__ float g_part[kNTiles * kRows];             // per-(ntile,row) exp-sums
__device__ float g_lz[kRows];                         // per-row logZ

__device__ __forceinline__ float sigf(float x) {
    return 1.0f / (1.0f + __expf(-x));
}
__device__ __forceinline__ float tanhfast(float x) {
    return 2.0f / (1.0f + __expf(-2.0f * x)) - 1.0f;
}
__device__ __forceinline__ uint32_t cvt_tf32(float x) {
    uint32_t u;
    asm("cvt.rna.tf32.f32 %0, %1;" : "=r"(u) : "f"(x));
    return u;
}
__device__ __forceinline__ void mma_tf32(float c[4], uint32_t a0, uint32_t a1,
                                         uint32_t a2, uint32_t a3,
                                         uint32_t b0, uint32_t b1) {
    asm("mma.sync.aligned.m16n8k8.row.col.f32.tf32.tf32.f32 "
        "{%0,%1,%2,%3}, {%4,%5,%6,%7}, {%8,%9}, {%0,%1,%2,%3};"
        : "+f"(c[0]), "+f"(c[1]), "+f"(c[2]), "+f"(c[3])
        : "r"(a0), "r"(a1), "r"(a2), "r"(a3), "r"(b0), "r"(b1));
}

// ---------------------------------------------------------------------------
// Kernel 0: Gx = x@W_ih.T + b_ih + b_hh (shared by both scan directions)
// ---------------------------------------------------------------------------
__global__ void gx_kernel(const int* __restrict__ tokens,
                          const float* __restrict__ emb,
                          const float* __restrict__ W_ih,
                          const float* __restrict__ b_ih,
                          const float* __restrict__ b_hh) {
    __shared__ float ws[kG * 33];
    __shared__ float xs[4][32];
    __shared__ float bb[kG];

    int tid = threadIdx.x;
    for (int i = tid; i < kG * kEMB; i += 256)
        ws[(i >> 5) * 33 + (i & 31)] = W_ih[i];
    if (tid < kG) bb[tid] = b_ih[tid] + b_hh[tid];

    int sb0 = blockIdx.x * 4;
    if (tid < 128) {
        int g = tid >> 5, k = tid & 31;
        xs[g][k] = emb[(size_t)tokens[sb0 + g] * kEMB + k];
    }
    __syncthreads();

    int g = tid >> 6;
    int j = tid & (kG - 1);
    const float* wr = ws + j * 33;
    float a0 = bb[j], a1 = 0.f, a2 = 0.f, a3 = 0.f;
#pragma unroll
    for (int k = 0; k < kEMB; k += 4) {
        a0 += xs[g][k + 0] * wr[k + 0];
        a1 += xs[g][k + 1] * wr[k + 1];
        a2 += xs[g][k + 2] * wr[k + 2];
        a3 += xs[g][k + 3] * wr[k + 3];
    }
    g_gx[(sb0 + g) * kG + j] = (a0 + a1) + (a2 + a3);
}

// ---------------------------------------------------------------------------
// Kernel 1: LSTM recurrence. 32 blocks = (2 dirs) x (16 batch lanes).
// ---------------------------------------------------------------------------
__global__ void lstm_kernel(const float* __restrict__ W_hh,
                            const float* __restrict__ init_h,
                            const float* __restrict__ init_c) {
    int dir = blockIdx.x >> 4;
    int b   = blockIdx.x & 15;
    int j   = threadIdx.x;

    __shared__ float h_sh[kHID];
    __shared__ float gact[kG];

    float w[kHID];
#pragma unroll
    for (int k = 0; k < kHID; ++k) w[k] = W_hh[j * kHID + k];

    float c_reg = 0.f, h_reg = 0.f;
    if (j < kHID) {
        h_reg = init_h[j];
        c_reg = init_c[j];
        h_sh[j] = h_reg;
    }
    __syncthreads();

    int p  = dir ? (kS - 1) : 0;
    int dp = dir ? -1 : 1;
    float gx_next = g_gx[(p * kB + b) * kG + j];

    for (int step = 0; step < kS; ++step, p += dp) {
        float gxv = gx_next;
        if (step < kS - 1) gx_next = g_gx[((p + dp) * kB + b) * kG + j];

        if (j < kHID)
            g_concat[(p * kB + b) * (2 * kHID) + dir * kHID + j] = h_reg;

        float a0 = 0.f, a1 = 0.f, a2 = 0.f, a3 = 0.f;
#pragma unroll
        for (int k = 0; k < kHID; k += 4) {
            a0 += w[k + 0] * h_sh[k + 0];
            a1 += w[k + 1] * h_sh[k + 1];
            a2 += w[k + 2] * h_sh[k + 2];
            a3 += w[k + 3] * h_sh[k + 3];
        }
        float pre = gxv + ((a0 + a1) + (a2 + a3));
        gact[j] = (j >= 32 && j < 48) ? tanhfast(pre) : sigf(pre);
        __syncthreads();

        if (j < kHID) {
            float ig = gact[j];
            float fg = gact[kHID + j];
            float gg = gact[2 * kHID + j];
            float og = gact[3 * kHID + j];
            c_reg = fg * c_reg + ig * gg;
            h_reg = og * tanhfast(c_reg);
            h_sh[j] = h_reg;
        }
        __syncthreads();
    }
}

// ---------------------------------------------------------------------------
// Kernel 2: tf32 tensor-core logits GEMM (two template passes).
// CTA = 128 rows x 128 cols, 8 warps (warp w owns rows w*16..w*16+15 x n128).
// Pass 1 (WRITE=false): MMA -> per-row sum(exp) -> g_part[ntile][row]
//                       (deterministic, no float atomics).
// Pass 2 (WRITE=true):  MMA with acc init = b_out - logZ -> smem transpose ->
//                       fully coalesced STG.128 of final log-probs.
// Frag LDS is bank-perfect: addr bank = gr*4+tg = laneid.
// ---------------------------------------------------------------------------
template <bool WRITE>
__global__ void __launch_bounds__(256, 2)
mma_pass(const float* __restrict__ W_out,
         const float* __restrict__ b_out,
         float* __restrict__ out) {
    __shared__ float A_sm[kMT * kAPad];   // tf32 bit patterns
    __shared__ float B_sm[kNT * kAPad];   // tf32 bit patterns
    __shared__ float bias_sm[kNT];
    __shared__ float lz_sm[kMT];

    int tid  = threadIdx.x;
    int warp = tid >> 5;
    int lane = tid & 31;
    int tg   = lane & 3;     // threadID-in-group
    int gr   = lane >> 2;    // groupID
    int n0   = blockIdx.x * kNT;
    int row0 = blockIdx.y * kMT;
    int mrow = warp * 16;

    // stage A (concat rows) with tf32 rounding; 128x32 floats
    {
        const float4* src = reinterpret_cast<const float4*>(
            g_concat + (size_t)row0 * 32);
        for (int i = tid; i < kMT * 8; i += 256) {
            float4 v = src[i];
            uint4 u = make_uint4(cvt_tf32(v.x), cvt_tf32(v.y),
                                 cvt_tf32(v.z), cvt_tf32(v.w));
            *reinterpret_cast<uint4*>(
                A_sm + (i >> 3) * kAPad + (i & 7) * 4) = u;
        }
    }
    // stage B (W_out rows n0..n0+127)
    {
        const float4* src = reinterpret_cast<const float4*>(
            W_out + (size_t)n0 * 32);
        for (int i = tid; i < kNT * 8; i += 256) {
            float4 v = src[i];
            uint4 u = make_uint4(cvt_tf32(v.x), cvt_tf32(v.y),
                                 cvt_tf32(v.z), cvt_tf32(v.w));
            *reinterpret_cast<uint4*>(
                B_sm + (i >> 3) * kAPad + (i & 7) * 4) = u;
        }
    }
    if (tid < kNT) bias_sm[tid] = b_out[n0 + tid];
    if (WRITE && tid < kMT) lz_sm[tid] = g_lz[row0 + tid];
    __syncthreads();

    // accumulators: 16 n-frags x 4
    float c[16][4];
#pragma unroll
    for (int f = 0; f < 16; ++f) {
        float bx = bias_sm[f * 8 + tg * 2];
        float by = bias_sm[f * 8 + tg * 2 + 1];
        if (WRITE) {
            float z0 = lz_sm[mrow + gr];
            float z1 = lz_sm[mrow + gr + 8];
            c[f][0] = bx - z0; c[f][1] = by - z0;
            c[f][2] = bx - z1; c[f][3] = by - z1;
        } else {
            c[f][0] = bx; c[f][1] = by;
            c[f][2] = bx; c[f][3] = by;
        }
    }

    const uint32_t* Ar0 =
        reinterpret_cast<const uint32_t*>(A_sm) + (mrow + gr) * kAPad;
    const uint32_t* Ar8 = Ar0 + 8 * kAPad;
    const uint32_t* Bp =
        reinterpret_cast<const uint32_t*>(B_sm) + gr * kAPad + tg;

#pragma unroll
    for (int kk = 0; kk < 32; kk += 8) {
        uint32_t a0 = Ar0[kk + tg];
        uint32_t a1 = Ar8[kk + tg];
        uint32_t a2 = Ar0[kk + 4 + tg];
        uint32_t a3 = Ar8[kk + 4 + tg];
#pragma unroll
        for (int f = 0; f < 16; ++f) {
            uint32_t b0 = Bp[f * 8 * kAPad + kk];
            uint32_t b1 = Bp[f * 8 * kAPad + kk + 4];
            mma_tf32(c[f], a0, a1, a2, a3, b0, b1);
        }
    }

    if (!WRITE) {
        // per-row sum(exp); rows mrow+gr and mrow+gr+8
        float s0 = 0.f, s1 = 0.f;
#pragma unroll
        for (int f = 0; f < 16; ++f) {
            s0 += __expf(c[f][0]) + __expf(c[f][1]);
            s1 += __expf(c[f][2]) + __expf(c[f][3]);
        }
        // reduce across the quad (lanes 4g..4g+3 share a row)
        s0 += __shfl_xor_sync(0xffffffffu, s0, 1);
        s0 += __shfl_xor_sync(0xffffffffu, s0, 2);
        s1 += __shfl_xor_sync(0xffffffffu, s1, 1);
        s1 += __shfl_xor_sync(0xffffffffu, s1, 2);
        if (tg == 0) {
            g_part[(size_t)blockIdx.x * kRows + row0 + mrow + gr]     = s0;
            g_part[(size_t)blockIdx.x * kRows + row0 + mrow + gr + 8] = s1;
        }
    } else {
        // epilogue: smem transpose (aliased over A_sm/B_sm) -> coalesced STG
        float* epi = A_sm;  // needs 128*68 = 8704 floats <= 2*128*36 = 9216
#pragma unroll
        for (int half = 0; half < 2; ++half) {
            __syncthreads();  // A/B reads (or prev chunk reads) complete
#pragma unroll
            for (int f = 0; f < 8; ++f) {
                int ff  = half * 8 + f;
                int col = f * 8 + tg * 2;
                *reinterpret_cast<float2*>(epi + (mrow + gr) * 68 + col) =
                    make_float2(c[ff][0], c[ff][1]);
                *reinterpret_cast<float2*>(epi + (mrow + gr + 8) * 68 + col) =
                    make_float2(c[ff][2], c[ff][3]);
            }
            __syncthreads();
            int c4 = (tid & 15) * 4;
            for (int rr = (tid >> 4); rr < kMT; rr += 16) {
                float4 v = *reinterpret_cast<const float4*>(epi + rr * 68 + c4);
                *reinterpret_cast<float4*>(
                    out + (size_t)(row0 + rr) * kV + n0 + half * 64 + c4) = v;
            }
        }
    }
}

// ---------------------------------------------------------------------------
// Kernel 3: logZ reduce over n-tiles (deterministic fixed-order sum)
// ---------------------------------------------------------------------------
__global__ void logz_kernel() {
    int row = blockIdx.x * 256 + threadIdx.x;
    float s = 0.f;
    for (int t = 0; t < kNTiles; ++t) s += g_part[(size_t)t * kRows + row];
    g_lz[row] = __logf(s);
}

// ---------------------------------------------------------------------------
extern "C" void kernel_launch(void* const* d_in, const int* in_sizes, int n_in,
                              void* d_out, int out_size) {
    const int*   tokens = (const int*)d_in[0];
    const float* emb    = (const float*)d_in[1];
    const float* W_ih   = (const float*)d_in[2];
    const float* W_hh   = (const float*)d_in[3];
    const float* b_ih   = (const float*)d_in[4];
    const float* b_hh   = (const float*)d_in[5];
    const float* W_out  = (const float*)d_in[6];
    const float* b_out  = (const float*)d_in[7];
    const float* init_h = (const float*)d_in[8];
    const float* init_c = (const float*)d_in[9];
    float* out = (float*)d_out;

    dim3 grid(kNTiles, kMTiles);

    gx_kernel<<<(kS * kB) / 4, 256>>>(tokens, emb, W_ih, b_ih, b_hh);
    lstm_kernel<<<32, 64>>>(W_hh, init_h, init_c);
    mma_pass<false><<<grid, 256>>>(W_out, b_out, out);
    logz_kernel<<<kRows / 256, 256>>>();
    mma_pass<true><<<grid, 256>>>(W_out, b_out, out);
}